// round 9
// baseline (speedup 1.0000x reference)
#include <cuda_runtime.h>
#include <cuda_bf16.h>
#include <cstdint>

// Problem: B=2, S=2048, D=1024, H=16, Dh=64, fp32.
//
// k-permutation (within each 8-col group of contraction dim):
// pos(i) = i<4 ? 2i : 2(i-4)+1, applied to BOTH operands -> dot invariant.
// Lets mma fragment loads ({gc, gc+4}) be one LDS.64.

#define B_   2
#define S_   2048
#define D_   1024
#define H_   16
#define DH_  64
#define HD_  (H_ * DH_)          // 1024
#define M_   (B_ * S_)           // 4096

#define QKV_ELEMS (B_ * S_ * HD_)

__device__ float g_q[QKV_ELEMS];      // tf32-rounded (gemm epilogue)
__device__ float g_k[QKV_ELEMS];
__device__ float g_v[QKV_ELEMS];
__device__ float g_attn[QKV_ELEMS];   // rounded + k-permuted (attn epilogue)
__device__ float g_rr[QKV_ELEMS];     // rounded + k-permuted residual
__device__ float g_wq[D_ * D_];
__device__ float g_wk[D_ * D_];
__device__ float g_wv[D_ * D_];
__device__ float g_woT[D_ * D_];      // rounded + k-permuted Wo^T

__device__ __forceinline__ float to_tf32(float x) {
    uint32_t r;
    asm("cvt.rna.tf32.f32 %0, %1;" : "=r"(r) : "f"(x));
    return __uint_as_float(r);
}

__device__ __forceinline__ uint32_t smem_u32(const void* p) {
    uint32_t a;
    asm("{ .reg .u64 t; cvta.to.shared.u64 t, %1; cvt.u32.u64 %0, t; }"
        : "=r"(a) : "l"(p));
    return a;
}

#define CP_ASYNC16(dst, src) \
    asm volatile("cp.async.cg.shared.global [%0], [%1], 16;" \
                 :: "r"(dst), "l"(src) : "memory")
#define CP_COMMIT() asm volatile("cp.async.commit_group;" ::: "memory")
#define CP_WAIT1()  asm volatile("cp.async.wait_group 1;" ::: "memory")

// mma.sync m16n8k8 tf32 (fragment mapping validated R4-R8):
// A: a0=A[gr][gc] a1=A[gr+8][gc] a2=A[gr][gc+4] a3=A[gr+8][gc+4]
// B: b0=B[n=gr][k=gc] b1=B[n=gr][k=gc+4]
// C: c0=C[gr][2gc] c1=C[gr][2gc+1] c2=C[gr+8][2gc] c3=C[gr+8][2gc+1]
__device__ __forceinline__ void mma_tf32(float* d, const float* a, const float* b) {
    asm volatile(
        "mma.sync.aligned.m16n8k8.row.col.f32.tf32.tf32.f32 "
        "{%0,%1,%2,%3}, {%4,%5,%6,%7}, {%8,%9}, {%0,%1,%2,%3};"
        : "+f"(d[0]), "+f"(d[1]), "+f"(d[2]), "+f"(d[3])
        : "r"(__float_as_uint(a[0])), "r"(__float_as_uint(a[1])),
          "r"(__float_as_uint(a[2])), "r"(__float_as_uint(a[3])),
          "r"(__float_as_uint(b[0])), "r"(__float_as_uint(b[1])));
}

// ===========================================================================
// tf32 mma GEMM: C[M,N] = A[M,K] . B[N,K]^T
// Inputs pre-rounded + k-permuted. GST=40 -> conflict-free LDS.64 frags.
// R9: double-buffered smem, ONE __syncthreads per k-iter, reg prefetch.
// 128x128 tile, BK=32, 256 threads, 8 warps @ 64x32. Dynamic smem 80KB.
// ===========================================================================
#define GST 40
#define STGF (128 * GST)                      // floats per operand per stage
#define GEMM_SMEM_BYTES (2 * 2 * STGF * 4)    // 81920

template <bool ROUND_OUT>
__device__ __forceinline__ void gemm_body(
    const float* __restrict__ A, const float* __restrict__ B,
    float* __restrict__ C, int M, int N, int K)
{
    extern __shared__ float gsm[];

    const int tid = threadIdx.x;
    const int lane = tid & 31;
    const int w = tid >> 5;
    const int wm = (w & 1) * 64;
    const int wn = (w >> 1) * 32;
    const int row0 = blockIdx.y * 128;
    const int col0 = blockIdx.x * 128;

    const int ar = tid >> 3;
    const int ac = (tid & 7) * 4;

    const float* Ap = A + (size_t)(row0 + ar) * K + ac;
    const float* Bp = B + (size_t)(col0 + ar) * K + ac;

    const int iters = K / 32;

    float4 pa[4], pb[4];
    // prologue: load kt=0, store stage 0, load kt=1, sync
#pragma unroll
    for (int p = 0; p < 4; p++) {
        pa[p] = *(const float4*)(Ap + (size_t)p * 32 * K);
        pb[p] = *(const float4*)(Bp + (size_t)p * 32 * K);
    }
    {
        float* As0 = gsm;
        float* Bs0 = gsm + STGF;
#pragma unroll
        for (int p = 0; p < 4; p++) {
            const int r = ar + p * 32;
            *(float4*)&As0[r * GST + ac] = pa[p];
            *(float4*)&Bs0[r * GST + ac] = pb[p];
        }
    }
#pragma unroll
    for (int p = 0; p < 4; p++) {
        pa[p] = *(const float4*)(Ap + 32 + (size_t)p * 32 * K);
        pb[p] = *(const float4*)(Bp + 32 + (size_t)p * 32 * K);
    }
    __syncthreads();

    float acc[4][4][4];
#pragma unroll
    for (int mi = 0; mi < 4; mi++)
#pragma unroll
        for (int ni = 0; ni < 4; ni++)
#pragma unroll
            for (int e = 0; e < 4; e++) acc[mi][ni][e] = 0.f;

    const int gr = lane >> 2;
    const int gc = lane & 3;

    for (int kt = 0; kt < iters; kt++) {
        // store regs (tile kt+1) into the other stage
        if (kt + 1 < iters) {
            float* Asn = gsm + ((kt + 1) & 1) * 2 * STGF;
            float* Bsn = Asn + STGF;
#pragma unroll
            for (int p = 0; p < 4; p++) {
                const int r = ar + p * 32;
                *(float4*)&Asn[r * GST + ac] = pa[p];
                *(float4*)&Bsn[r * GST + ac] = pb[p];
            }
        }
        // prefetch tile kt+2
        if (kt + 2 < iters) {
#pragma unroll
            for (int p = 0; p < 4; p++) {
                pa[p] = *(const float4*)(Ap + (kt + 2) * 32 + (size_t)p * 32 * K);
                pb[p] = *(const float4*)(Bp + (kt + 2) * 32 + (size_t)p * 32 * K);
            }
        }

        // compute from stage kt%2
        const float* As = gsm + (kt & 1) * 2 * STGF;
        const float* Bs = As + STGF;
#pragma unroll
        for (int ks = 0; ks < 4; ks++) {
            const int k0 = ks * 8 + 2 * gc;
            float af[4][4];
#pragma unroll
            for (int mi = 0; mi < 4; mi++) {
                const float2 alo = *(const float2*)&As[(wm + mi * 16 + gr) * GST + k0];
                const float2 ahi = *(const float2*)&As[(wm + mi * 16 + gr + 8) * GST + k0];
                af[mi][0] = alo.x; af[mi][1] = ahi.x;
                af[mi][2] = alo.y; af[mi][3] = ahi.y;
            }
            float bf[4][2];
#pragma unroll
            for (int ni = 0; ni < 4; ni++) {
                const float2 b2 = *(const float2*)&Bs[(wn + ni * 8 + gr) * GST + k0];
                bf[ni][0] = b2.x; bf[ni][1] = b2.y;
            }
#pragma unroll
            for (int mi = 0; mi < 4; mi++)
#pragma unroll
                for (int ni = 0; ni < 4; ni++)
                    mma_tf32(acc[mi][ni], af[mi], bf[ni]);
        }
        __syncthreads();   // publish stage (kt+1)%2; guard next store vs this compute
    }

#pragma unroll
    for (int mi = 0; mi < 4; mi++) {
        const int r = row0 + wm + mi * 16 + gr;
#pragma unroll
        for (int ni = 0; ni < 4; ni++) {
            const int c = col0 + wn + ni * 8 + 2 * gc;
            if (ROUND_OUT) {
#pragma unroll
                for (int e = 0; e < 4; e++) acc[mi][ni][e] = to_tf32(acc[mi][ni][e]);
            }
            *(float2*)(C + (size_t)r * N + c) =
                make_float2(acc[mi][ni][0], acc[mi][ni][1]);
            *(float2*)(C + (size_t)(r + 8) * N + c) =
                make_float2(acc[mi][ni][2], acc[mi][ni][3]);
        }
    }
}

__global__ void __launch_bounds__(256) gemm_mma_nt(
    const float* __restrict__ A, const float* __restrict__ B,
    float* __restrict__ C, int M, int N, int K)
{
    gemm_body<false>(A, B, C, M, N, K);
}

__global__ void __launch_bounds__(256) gemm_mma_qkv(
    const float* __restrict__ A,
    const float* __restrict__ Wq, const float* __restrict__ Wk,
    const float* __restrict__ Wv,
    float* __restrict__ q, float* __restrict__ k, float* __restrict__ v,
    int M, int N, int K)
{
    const int z = blockIdx.z;
    const float* Bp = (z == 0) ? Wq : (z == 1) ? Wk : Wv;
    float* Cp = (z == 0) ? q : (z == 1) ? k : v;
    gemm_body<true>(A, Bp, Cp, M, N, K);
}

// ===========================================================================
// Pre-rounding + k-permutation kernels
// ===========================================================================
__global__ void round_perm_k(const float* __restrict__ in,
                             float* __restrict__ out, int n8)
{
    int i = blockIdx.x * blockDim.x + threadIdx.x;
    if (i < n8) {
        const float4 lo = *(const float4*)(in + (size_t)i * 8);
        const float4 hi = *(const float4*)(in + (size_t)i * 8 + 4);
        *(float4*)(out + (size_t)i * 8) =
            make_float4(to_tf32(lo.x), to_tf32(hi.x), to_tf32(lo.y), to_tf32(hi.y));
        *(float4*)(out + (size_t)i * 8 + 4) =
            make_float4(to_tf32(lo.z), to_tf32(hi.z), to_tf32(lo.w), to_tf32(hi.w));
    }
}

__global__ void round_perm_w3(const float* __restrict__ Wq,
                              const float* __restrict__ Wk,
                              const float* __restrict__ Wv,
                              float* __restrict__ oq, float* __restrict__ ok,
                              float* __restrict__ ov, int n8)
{
    const int z = blockIdx.z;
    const float* in = (z == 0) ? Wq : (z == 1) ? Wk : Wv;
    float* out = (z == 0) ? oq : (z == 1) ? ok : ov;
    int i = blockIdx.x * blockDim.x + threadIdx.x;
    if (i < n8) {
        const float4 lo = *(const float4*)(in + (size_t)i * 8);
        const float4 hi = *(const float4*)(in + (size_t)i * 8 + 4);
        *(float4*)(out + (size_t)i * 8) =
            make_float4(to_tf32(lo.x), to_tf32(hi.x), to_tf32(lo.y), to_tf32(hi.y));
        *(float4*)(out + (size_t)i * 8 + 4) =
            make_float4(to_tf32(lo.z), to_tf32(hi.z), to_tf32(lo.w), to_tf32(hi.w));
    }
}

__global__ void transpose_round_perm(const float* __restrict__ in,
                                     float* __restrict__ out)
{
    __shared__ float t[32][33];
    const int bx = blockIdx.x * 32, by = blockIdx.y * 32;
    const int x = threadIdx.x, y = threadIdx.y;
#pragma unroll
    for (int j = 0; j < 32; j += 8)
        t[y + j][x] = in[(size_t)(by + y + j) * D_ + bx + x];
    __syncthreads();
    const int xi = x & 7;
    const int px = (x & 24) | (xi < 4 ? 2 * xi : 2 * (xi - 4) + 1);
#pragma unroll
    for (int j = 0; j < 32; j += 8)
        out[(size_t)(bx + y + j) * D_ + by + px] = to_tf32(t[x][y + j]);
}

// ===========================================================================
// Flash attention (causal) tf32 mma.
// R9: 3-stage cp.async K/V pipeline, ONE __syncthreads per kv tile.
// Stage s: Ks_s [64][AST], Vs_s [64][AST]; Ps after all stages.
// LPT block order (qt reversed). Inputs pre-rounded.
// ===========================================================================
#define AST 68
#define KV_STG_FLOATS (2 * 64 * AST)                         // per stage
#define ATTN_SMEM_FLOATS (3 * KV_STG_FLOATS + 128 * AST)
#define ATTN_SMEM_BYTES  (ATTN_SMEM_FLOATS * 4)              // 139264

__global__ void __launch_bounds__(256) attn_mma(
    const float* __restrict__ Q, const float* __restrict__ K,
    const float* __restrict__ V, float* __restrict__ O)
{
    extern __shared__ float sma[];
    float* Ps = sma + 3 * KV_STG_FLOATS;

    const int tid = threadIdx.x;
    const int lane = tid & 31;
    const int w = tid >> 5;
    const int gr = lane >> 2;
    const int gc = lane & 3;

    const int qt = (gridDim.x - 1) - blockIdx.x;   // LPT: heavy blocks first
    const int bh = blockIdx.y;
    const int b = bh >> 4, h = bh & 15;
    const int q0 = qt * 128;
    const size_t base = (size_t)b * S_ * HD_ + (size_t)h * DH_;
    const int ktiles = 2 * qt + 2;

    // cp.async loader geometry: thread -> row tid>>2, 4 col-chunks of 16B
    const int cr = tid >> 2;            // 0..63
    const int cb = tid & 3;             // 0..3
    const uint32_t smb = smem_u32(sma);

    // Prologue: issue tiles 0 and 1 (ktiles >= 2 always)
#pragma unroll
    for (int s = 0; s < 2; s++) {
        const int kv0 = s * 64;
        const uint32_t ks_d = smb + (uint32_t)(s * KV_STG_FLOATS) * 4;
        const uint32_t vs_d = ks_d + (uint32_t)(64 * AST) * 4;
        const float* ksrc = K + base + (size_t)(kv0 + cr) * HD_;
        const float* vsrc = V + base + (size_t)(kv0 + cr) * HD_;
#pragma unroll
        for (int cc = 0; cc < 4; cc++) {
            const int col = (cb + cc * 4) * 4;
            CP_ASYNC16(ks_d + (uint32_t)(cr * AST + col) * 4, ksrc + col);
            CP_ASYNC16(vs_d + (uint32_t)(cr * AST + col) * 4, vsrc + col);
        }
        CP_COMMIT();
    }

    // Stage Q into Ps (already tf32-rounded), pull A-frags to registers
    {
        const int r = tid >> 4;
        const int c = (tid & 15) << 2;
#pragma unroll
        for (int rr = 0; rr < 128; rr += 16) {
            *(float4*)&Ps[(rr + r) * AST + c] =
                *(const float4*)(Q + base + (size_t)(q0 + rr + r) * HD_ + c);
        }
    }
    __syncthreads();

    float qf[8][4];
#pragma unroll
    for (int ks = 0; ks < 8; ks++) {
        const float* qp = &Ps[(w * 16 + gr) * AST + ks * 8 + gc];
        qf[ks][0] = qp[0];
        qf[ks][1] = qp[8 * AST];
        qf[ks][2] = qp[4];
        qf[ks][3] = qp[8 * AST + 4];
    }
    __syncthreads();   // qf read before Ps is overwritten with P

    float o[8][4];
#pragma unroll
    for (int ni = 0; ni < 8; ni++)
#pragma unroll
        for (int e = 0; e < 4; e++) o[ni][e] = 0.f;
    float m0 = -1e30f, m1 = -1e30f, l0 = 0.f, l1 = 0.f;

    const int qg0 = q0 + w * 16 + gr;
    const int qg1 = qg0 + 8;

    for (int kt = 0; kt < ktiles; kt++) {
        // tile kt ready (per-thread), then publish to all threads
        CP_WAIT1();
        __syncthreads();

        // issue tile kt+2 into stage (kt+2)%3 (last read at iter kt-1; safe
        // after the sync above). Commit every iter to keep group count in step.
        if (kt + 2 < ktiles) {
            const int kv0n = (kt + 2) * 64;
            const int sn = (kt + 2) % 3;
            const uint32_t ks_d = smb + (uint32_t)(sn * KV_STG_FLOATS) * 4;
            const uint32_t vs_d = ks_d + (uint32_t)(64 * AST) * 4;
            const float* ksrc = K + base + (size_t)(kv0n + cr) * HD_;
            const float* vsrc = V + base + (size_t)(kv0n + cr) * HD_;
#pragma unroll
            for (int cc = 0; cc < 4; cc++) {
                const int col = (cb + cc * 4) * 4;
                CP_ASYNC16(ks_d + (uint32_t)(cr * AST + col) * 4, ksrc + col);
                CP_ASYNC16(vs_d + (uint32_t)(cr * AST + col) * 4, vsrc + col);
            }
        }
        CP_COMMIT();

        const int kv0 = kt * 64;
        if (kv0 > q0 + w * 16 + 15) continue;   // fully masked warp-tile

        const float* Ks = sma + (kt % 3) * KV_STG_FLOATS;
        const float* Vs = Ks + 64 * AST;

        // S = Q . K^T
        float s[8][4];
#pragma unroll
        for (int ni = 0; ni < 8; ni++)
#pragma unroll
            for (int e = 0; e < 4; e++) s[ni][e] = 0.f;

#pragma unroll
        for (int ks = 0; ks < 8; ks++) {
            const int k0 = ks * 8 + gc;
            float bf[8][2];
#pragma unroll
            for (int ni = 0; ni < 8; ni++) {
                const float* bp = &Ks[(ni * 8 + gr) * AST + k0];
                bf[ni][0] = bp[0];
                bf[ni][1] = bp[4];
            }
#pragma unroll
            for (int ni = 0; ni < 8; ni++)
                mma_tf32(s[ni], qf[ks], bf[ni]);
        }

        const float scale = 0.125f;
        if (kv0 + 63 > q0 + w * 16) {
#pragma unroll
            for (int ni = 0; ni < 8; ni++) {
                const int c0 = kv0 + ni * 8 + 2 * gc;
                s[ni][0] = (c0     <= qg0) ? s[ni][0] * scale : -1e30f;
                s[ni][1] = (c0 + 1 <= qg0) ? s[ni][1] * scale : -1e30f;
                s[ni][2] = (c0     <= qg1) ? s[ni][2] * scale : -1e30f;
                s[ni][3] = (c0 + 1 <= qg1) ? s[ni][3] * scale : -1e30f;
            }
        } else {
#pragma unroll
            for (int ni = 0; ni < 8; ni++)
#pragma unroll
                for (int e = 0; e < 4; e++) s[ni][e] *= scale;
        }

        float rmax0 = -1e30f, rmax1 = -1e30f;
#pragma unroll
        for (int ni = 0; ni < 8; ni++) {
            rmax0 = fmaxf(rmax0, fmaxf(s[ni][0], s[ni][1]));
            rmax1 = fmaxf(rmax1, fmaxf(s[ni][2], s[ni][3]));
        }
        rmax0 = fmaxf(rmax0, __shfl_xor_sync(0xffffffffu, rmax0, 1));
        rmax0 = fmaxf(rmax0, __shfl_xor_sync(0xffffffffu, rmax0, 2));
        rmax1 = fmaxf(rmax1, __shfl_xor_sync(0xffffffffu, rmax1, 1));
        rmax1 = fmaxf(rmax1, __shfl_xor_sync(0xffffffffu, rmax1, 2));

        const float mn0 = fmaxf(m0, rmax0);
        const float mn1 = fmaxf(m1, rmax1);
        const float corr0 = __expf(m0 - mn0);
        const float corr1 = __expf(m1 - mn1);

        float ps0 = 0.f, ps1 = 0.f;
#pragma unroll
        for (int ni = 0; ni < 8; ni++) {
            s[ni][0] = __expf(s[ni][0] - mn0);
            s[ni][1] = __expf(s[ni][1] - mn0);
            s[ni][2] = __expf(s[ni][2] - mn1);
            s[ni][3] = __expf(s[ni][3] - mn1);
            ps0 += s[ni][0] + s[ni][1];
            ps1 += s[ni][2] + s[ni][3];
        }
        ps0 += __shfl_xor_sync(0xffffffffu, ps0, 1);
        ps0 += __shfl_xor_sync(0xffffffffu, ps0, 2);
        ps1 += __shfl_xor_sync(0xffffffffu, ps1, 1);
        ps1 += __shfl_xor_sync(0xffffffffu, ps1, 2);

        l0 = l0 * corr0 + ps0;  m0 = mn0;
        l1 = l1 * corr1 + ps1;  m1 = mn1;

#pragma unroll
        for (int ni = 0; ni < 8; ni++) {
            o[ni][0] *= corr0; o[ni][1] *= corr0;
            o[ni][2] *= corr1; o[ni][3] *= corr1;
        }

        // P -> Ps (tf32-rounded); warp-private rows
        {
            float* p0 = &Ps[(w * 16 + gr) * AST + 2 * gc];
            float* p1 = p0 + 8 * AST;
#pragma unroll
            for (int ni = 0; ni < 8; ni++) {
                *(float2*)(p0 + ni * 8) =
                    make_float2(to_tf32(s[ni][0]), to_tf32(s[ni][1]));
                *(float2*)(p1 + ni * 8) =
                    make_float2(to_tf32(s[ni][2]), to_tf32(s[ni][3]));
            }
        }
        __syncwarp();

        // O += P . V
#pragma unroll
        for (int ks = 0; ks < 8; ks++) {
            const float* ap = &Ps[(w * 16 + gr) * AST + ks * 8 + gc];
            float af[4];
            af[0] = ap[0];
            af[1] = ap[8 * AST];
            af[2] = ap[4];
            af[3] = ap[8 * AST + 4];
            const float* v0 = &Vs[(ks * 8 + gc) * AST + gr];
            const float* v1 = &Vs[(ks * 8 + gc + 4) * AST + gr];
            float bf[8][2];
#pragma unroll
            for (int ni = 0; ni < 8; ni++) {
                bf[ni][0] = v0[ni * 8];
                bf[ni][1] = v1[ni * 8];
            }
#pragma unroll
            for (int ni = 0; ni < 8; ni++)
                mma_tf32(o[ni], af, bf[ni]);
        }
    }

    // Epilogue: rounded + k-permuted stores (out-proj consumes as A).
    const float inv0 = 1.f / l0;
    const float inv1 = 1.f / l1;
    const int p0 = ((gc & 1) << 2) | (gc >> 1);
#pragma unroll
    for (int ni = 0; ni < 8; ni++) {
        const int c = ni * 8;
        float* r0 = (float*)(O + base + (size_t)qg0 * HD_ + c);
        float* r1 = (float*)(O + base + (size_t)qg1 * HD_ + c);
        r0[p0]     = to_tf32(o[ni][0] * inv0);
        r0[p0 + 2] = to_tf32(o[ni][1] * inv0);
        r1[p0]     = to_tf32(o[ni][2] * inv1);
        r1[p0 + 2] = to_tf32(o[ni][3] * inv1);
    }
}

// ===========================================================================
// Host side
// ===========================================================================
extern "C" void kernel_launch(void* const* d_in, const int* in_sizes, int n_in,
                              void* d_out, int out_size)
{
    const float* residual = (const float*)d_in[0];
    const float* Wq = (const float*)d_in[1];
    const float* Wk = (const float*)d_in[2];
    const float* Wv = (const float*)d_in[3];
    const float* Wo = (const float*)d_in[4];
    float* out = (float*)d_out;

    float *q, *k, *v, *attn, *rr, *wq, *wk, *wv, *woT;
    cudaGetSymbolAddress((void**)&q,    g_q);
    cudaGetSymbolAddress((void**)&k,    g_k);
    cudaGetSymbolAddress((void**)&v,    g_v);
    cudaGetSymbolAddress((void**)&attn, g_attn);
    cudaGetSymbolAddress((void**)&rr,   g_rr);
    cudaGetSymbolAddress((void**)&wq,   g_wq);
    cudaGetSymbolAddress((void**)&wk,   g_wk);
    cudaGetSymbolAddress((void**)&wv,   g_wv);
    cudaGetSymbolAddress((void**)&woT,  g_woT);

    cudaFuncSetAttribute(attn_mma,
                         cudaFuncAttributeMaxDynamicSharedMemorySize,
                         ATTN_SMEM_BYTES);
    cudaFuncSetAttribute(gemm_mma_nt,
                         cudaFuncAttributeMaxDynamicSharedMemorySize,
                         GEMM_SMEM_BYTES);
    cudaFuncSetAttribute(gemm_mma_qkv,
                         cudaFuncAttributeMaxDynamicSharedMemorySize,
                         GEMM_SMEM_BYTES);

    dim3 blk(256);

    // Round + permute GEMM operands
    round_perm_k<<<QKV_ELEMS / 8 / 256, 256>>>(residual, rr, QKV_ELEMS / 8);
    round_perm_w3<<<dim3(D_ * D_ / 8 / 256, 1, 3), 256>>>(Wq, Wk, Wv,
                                                          wq, wk, wv,
                                                          D_ * D_ / 8);
    transpose_round_perm<<<dim3(32, 32), dim3(32, 8)>>>(Wo, woT);

    // Fused QKV projections (tf32-rounded outputs)
    dim3 gqkv(D_ / 128, M_ / 128, 3);
    gemm_mma_qkv<<<gqkv, blk, GEMM_SMEM_BYTES>>>(rr, wq, wk, wv, q, k, v,
                                                 M_, D_, D_);

    // Causal flash attention (cp.async pipeline, LPT order)
    dim3 gattn(S_ / 128, B_ * H_);
    attn_mma<<<gattn, blk, ATTN_SMEM_BYTES>>>(q, k, v, attn);

    // Output projection
    dim3 gg(D_ / 128, M_ / 128);
    gemm_mma_nt<<<gg, blk, GEMM_SMEM_BYTES>>>(attn, woT, out, M_, D_, D_);
}

// round 10
// speedup vs baseline: 1.0084x; 1.0084x over previous
#include <cuda_runtime.h>
#include <cuda_bf16.h>
#include <cstdint>

// Problem: B=2, S=2048, D=1024, H=16, Dh=64, fp32.
//
// k-permutation (within each 8-col group of contraction dim):
// pos(i) = i<4 ? 2i : 2(i-4)+1, applied to BOTH operands -> dot invariant.
// Lets mma fragment loads ({gc, gc+4}) be one LDS.64.

#define B_   2
#define S_   2048
#define D_   1024
#define H_   16
#define DH_  64
#define HD_  (H_ * DH_)          // 1024
#define M_   (B_ * S_)           // 4096

#define QKV_ELEMS (B_ * S_ * HD_)

__device__ float g_q[QKV_ELEMS];      // tf32-rounded (gemm epilogue)
__device__ float g_k[QKV_ELEMS];
__device__ float g_v[QKV_ELEMS];
__device__ float g_attn[QKV_ELEMS];   // rounded + k-permuted (attn epilogue)
__device__ float g_rr[QKV_ELEMS];     // rounded + k-permuted residual
__device__ float g_wq[D_ * D_];
__device__ float g_wk[D_ * D_];
__device__ float g_wv[D_ * D_];
__device__ float g_woT[D_ * D_];      // rounded + k-permuted Wo^T

__device__ __forceinline__ float to_tf32(float x) {
    uint32_t r;
    asm("cvt.rna.tf32.f32 %0, %1;" : "=r"(r) : "f"(x));
    return __uint_as_float(r);
}

// mma.sync m16n8k8 tf32 (fragment mapping validated R4-R9):
// A: a0=A[gr][gc] a1=A[gr+8][gc] a2=A[gr][gc+4] a3=A[gr+8][gc+4]
// B: b0=B[n=gr][k=gc] b1=B[n=gr][k=gc+4]
// C: c0=C[gr][2gc] c1=C[gr][2gc+1] c2=C[gr+8][2gc] c3=C[gr+8][2gc+1]
__device__ __forceinline__ void mma_tf32(float* d, const float* a, const float* b) {
    asm volatile(
        "mma.sync.aligned.m16n8k8.row.col.f32.tf32.tf32.f32 "
        "{%0,%1,%2,%3}, {%4,%5,%6,%7}, {%8,%9}, {%0,%1,%2,%3};"
        : "+f"(d[0]), "+f"(d[1]), "+f"(d[2]), "+f"(d[3])
        : "r"(__float_as_uint(a[0])), "r"(__float_as_uint(a[1])),
          "r"(__float_as_uint(a[2])), "r"(__float_as_uint(a[3])),
          "r"(__float_as_uint(b[0])), "r"(__float_as_uint(b[1])));
}

// ===========================================================================
// tf32 mma GEMM: C[M,N] = A[M,K] . B[N,K]^T
// R10: 512 threads, 16 warps @ 32x32 warp tiles (acc 32 regs/thread ->
// ~2x resident warps/SM vs R8). R8 loop structure (single buffer,
// 2 syncs/iter, register prefetch). GST=40 conflict-free LDS.64 frags.
// ===========================================================================
#define GST 40

template <bool ROUND_OUT>
__device__ __forceinline__ void gemm_body(
    const float* __restrict__ A, const float* __restrict__ B,
    float* __restrict__ C, int M, int N, int K)
{
    __shared__ float As[128 * GST];
    __shared__ float Bs[128 * GST];

    const int tid = threadIdx.x;
    const int lane = tid & 31;
    const int w = tid >> 5;            // 0..15
    const int wm = (w & 3) * 32;       // 4 warp rows
    const int wn = (w >> 2) * 32;      // 4 warp cols
    const int row0 = blockIdx.y * 128;
    const int col0 = blockIdx.x * 128;

    // loader: thread -> rows ar, ar+64; one float4 at col ac each
    const int ar = tid >> 3;           // 0..63
    const int ac = (tid & 7) * 4;      // 0,4,...,28

    const float* Ap = A + (size_t)(row0 + ar) * K + ac;
    const float* Bp = B + (size_t)(col0 + ar) * K + ac;

    float4 pa[2], pb[2];
#pragma unroll
    for (int p = 0; p < 2; p++) {
        pa[p] = *(const float4*)(Ap + (size_t)p * 64 * K);
        pb[p] = *(const float4*)(Bp + (size_t)p * 64 * K);
    }

    float acc[2][4][4];
#pragma unroll
    for (int mi = 0; mi < 2; mi++)
#pragma unroll
        for (int ni = 0; ni < 4; ni++)
#pragma unroll
            for (int e = 0; e < 4; e++) acc[mi][ni][e] = 0.f;

    const int gr = lane >> 2;
    const int gc = lane & 3;
    const int iters = K / 32;

    for (int kt = 0;;) {
#pragma unroll
        for (int p = 0; p < 2; p++) {
            const int r = ar + p * 64;
            *(float4*)&As[r * GST + ac] = pa[p];
            *(float4*)&Bs[r * GST + ac] = pb[p];
        }
        __syncthreads();

        kt++;
        if (kt < iters) {
#pragma unroll
            for (int p = 0; p < 2; p++) {
                pa[p] = *(const float4*)(Ap + kt * 32 + (size_t)p * 64 * K);
                pb[p] = *(const float4*)(Bp + kt * 32 + (size_t)p * 64 * K);
            }
        }

#pragma unroll
        for (int ks = 0; ks < 4; ks++) {
            const int k0 = ks * 8 + 2 * gc;
            float af[2][4];
#pragma unroll
            for (int mi = 0; mi < 2; mi++) {
                const float2 alo = *(const float2*)&As[(wm + mi * 16 + gr) * GST + k0];
                const float2 ahi = *(const float2*)&As[(wm + mi * 16 + gr + 8) * GST + k0];
                af[mi][0] = alo.x; af[mi][1] = ahi.x;
                af[mi][2] = alo.y; af[mi][3] = ahi.y;
            }
            float bf[4][2];
#pragma unroll
            for (int ni = 0; ni < 4; ni++) {
                const float2 b2 = *(const float2*)&Bs[(wn + ni * 8 + gr) * GST + k0];
                bf[ni][0] = b2.x; bf[ni][1] = b2.y;
            }
#pragma unroll
            for (int mi = 0; mi < 2; mi++)
#pragma unroll
                for (int ni = 0; ni < 4; ni++)
                    mma_tf32(acc[mi][ni], af[mi], bf[ni]);
        }

        if (kt >= iters) break;
        __syncthreads();
    }

#pragma unroll
    for (int mi = 0; mi < 2; mi++) {
        const int r = row0 + wm + mi * 16 + gr;
#pragma unroll
        for (int ni = 0; ni < 4; ni++) {
            const int c = col0 + wn + ni * 8 + 2 * gc;
            if (ROUND_OUT) {
#pragma unroll
                for (int e = 0; e < 4; e++) acc[mi][ni][e] = to_tf32(acc[mi][ni][e]);
            }
            *(float2*)(C + (size_t)r * N + c) =
                make_float2(acc[mi][ni][0], acc[mi][ni][1]);
            *(float2*)(C + (size_t)(r + 8) * N + c) =
                make_float2(acc[mi][ni][2], acc[mi][ni][3]);
        }
    }
}

__global__ void __launch_bounds__(512) gemm_mma_nt(
    const float* __restrict__ A, const float* __restrict__ B,
    float* __restrict__ C, int M, int N, int K)
{
    gemm_body<false>(A, B, C, M, N, K);
}

__global__ void __launch_bounds__(512) gemm_mma_qkv(
    const float* __restrict__ A,
    const float* __restrict__ Wq, const float* __restrict__ Wk,
    const float* __restrict__ Wv,
    float* __restrict__ q, float* __restrict__ k, float* __restrict__ v,
    int M, int N, int K)
{
    const int z = blockIdx.z;
    const float* Bp = (z == 0) ? Wq : (z == 1) ? Wk : Wv;
    float* Cp = (z == 0) ? q : (z == 1) ? k : v;
    gemm_body<true>(A, Bp, Cp, M, N, K);
}

// ===========================================================================
// Pre-rounding + k-permutation kernels
// ===========================================================================
__global__ void round_perm_k(const float* __restrict__ in,
                             float* __restrict__ out, int n8)
{
    int i = blockIdx.x * blockDim.x + threadIdx.x;
    if (i < n8) {
        const float4 lo = *(const float4*)(in + (size_t)i * 8);
        const float4 hi = *(const float4*)(in + (size_t)i * 8 + 4);
        *(float4*)(out + (size_t)i * 8) =
            make_float4(to_tf32(lo.x), to_tf32(hi.x), to_tf32(lo.y), to_tf32(hi.y));
        *(float4*)(out + (size_t)i * 8 + 4) =
            make_float4(to_tf32(lo.z), to_tf32(hi.z), to_tf32(lo.w), to_tf32(hi.w));
    }
}

__global__ void round_perm_w3(const float* __restrict__ Wq,
                              const float* __restrict__ Wk,
                              const float* __restrict__ Wv,
                              float* __restrict__ oq, float* __restrict__ ok,
                              float* __restrict__ ov, int n8)
{
    const int z = blockIdx.z;
    const float* in = (z == 0) ? Wq : (z == 1) ? Wk : Wv;
    float* out = (z == 0) ? oq : (z == 1) ? ok : ov;
    int i = blockIdx.x * blockDim.x + threadIdx.x;
    if (i < n8) {
        const float4 lo = *(const float4*)(in + (size_t)i * 8);
        const float4 hi = *(const float4*)(in + (size_t)i * 8 + 4);
        *(float4*)(out + (size_t)i * 8) =
            make_float4(to_tf32(lo.x), to_tf32(hi.x), to_tf32(lo.y), to_tf32(hi.y));
        *(float4*)(out + (size_t)i * 8 + 4) =
            make_float4(to_tf32(lo.z), to_tf32(hi.z), to_tf32(lo.w), to_tf32(hi.w));
    }
}

__global__ void transpose_round_perm(const float* __restrict__ in,
                                     float* __restrict__ out)
{
    __shared__ float t[32][33];
    const int bx = blockIdx.x * 32, by = blockIdx.y * 32;
    const int x = threadIdx.x, y = threadIdx.y;
#pragma unroll
    for (int j = 0; j < 32; j += 8)
        t[y + j][x] = in[(size_t)(by + y + j) * D_ + bx + x];
    __syncthreads();
    const int xi = x & 7;
    const int px = (x & 24) | (xi < 4 ? 2 * xi : 2 * (xi - 4) + 1);
#pragma unroll
    for (int j = 0; j < 32; j += 8)
        out[(size_t)(bx + y + j) * D_ + by + px] = to_tf32(t[x][y + j]);
}

// ===========================================================================
// Flash attention (causal) tf32 mma — R8 version verbatim (best measured):
// pre-rounded inputs (pure-copy tile loads), LPT block order.
// ===========================================================================
#define AST 68
#define ATTN_SMEM_FLOATS (64 * AST + 64 * AST + 128 * AST)
#define ATTN_SMEM_BYTES  (ATTN_SMEM_FLOATS * 4)

__global__ void __launch_bounds__(256) attn_mma(
    const float* __restrict__ Q, const float* __restrict__ K,
    const float* __restrict__ V, float* __restrict__ O)
{
    extern __shared__ float sma[];
    float* Ks = sma;
    float* Vs = sma + 64 * AST;
    float* Ps = sma + 128 * AST;

    const int tid = threadIdx.x;
    const int lane = tid & 31;
    const int w = tid >> 5;
    const int gr = lane >> 2;
    const int gc = lane & 3;

    const int qt = (gridDim.x - 1) - blockIdx.x;   // LPT: heavy blocks first
    const int bh = blockIdx.y;
    const int b = bh >> 4, h = bh & 15;
    const int q0 = qt * 128;
    const size_t base = (size_t)b * S_ * HD_ + (size_t)h * DH_;

    {
        const int r = tid >> 4;
        const int c = (tid & 15) << 2;
#pragma unroll
        for (int rr = 0; rr < 128; rr += 16) {
            *(float4*)&Ps[(rr + r) * AST + c] =
                *(const float4*)(Q + base + (size_t)(q0 + rr + r) * HD_ + c);
        }
    }
    __syncthreads();

    float qf[8][4];
#pragma unroll
    for (int ks = 0; ks < 8; ks++) {
        const float* qp = &Ps[(w * 16 + gr) * AST + ks * 8 + gc];
        qf[ks][0] = qp[0];
        qf[ks][1] = qp[8 * AST];
        qf[ks][2] = qp[4];
        qf[ks][3] = qp[8 * AST + 4];
    }
    __syncthreads();

    float o[8][4];
#pragma unroll
    for (int ni = 0; ni < 8; ni++)
#pragma unroll
        for (int e = 0; e < 4; e++) o[ni][e] = 0.f;
    float m0 = -1e30f, m1 = -1e30f, l0 = 0.f, l1 = 0.f;

    const int qg0 = q0 + w * 16 + gr;
    const int qg1 = qg0 + 8;
    const int ktiles = 2 * qt + 2;

    for (int kt = 0; kt < ktiles; kt++) {
        const int kv0 = kt * 64;
        __syncthreads();
        {
            const int r = tid >> 4;
            const int c = (tid & 15) << 2;
#pragma unroll
            for (int rr = 0; rr < 64; rr += 16) {
                const int row = rr + r;
                *(float4*)&Ks[row * AST + c] =
                    *(const float4*)(K + base + (size_t)(kv0 + row) * HD_ + c);
                *(float4*)&Vs[row * AST + c] =
                    *(const float4*)(V + base + (size_t)(kv0 + row) * HD_ + c);
            }
        }
        __syncthreads();

        if (kv0 > q0 + w * 16 + 15) continue;

        float s[8][4];
#pragma unroll
        for (int ni = 0; ni < 8; ni++)
#pragma unroll
            for (int e = 0; e < 4; e++) s[ni][e] = 0.f;

#pragma unroll
        for (int ks = 0; ks < 8; ks++) {
            const int k0 = ks * 8 + gc;
            float bf[8][2];
#pragma unroll
            for (int ni = 0; ni < 8; ni++) {
                const float* bp = &Ks[(ni * 8 + gr) * AST + k0];
                bf[ni][0] = bp[0];
                bf[ni][1] = bp[4];
            }
#pragma unroll
            for (int ni = 0; ni < 8; ni++)
                mma_tf32(s[ni], qf[ks], bf[ni]);
        }

        const float scale = 0.125f;
        if (kv0 + 63 > q0 + w * 16) {
#pragma unroll
            for (int ni = 0; ni < 8; ni++) {
                const int c0 = kv0 + ni * 8 + 2 * gc;
                s[ni][0] = (c0     <= qg0) ? s[ni][0] * scale : -1e30f;
                s[ni][1] = (c0 + 1 <= qg0) ? s[ni][1] * scale : -1e30f;
                s[ni][2] = (c0     <= qg1) ? s[ni][2] * scale : -1e30f;
                s[ni][3] = (c0 + 1 <= qg1) ? s[ni][3] * scale : -1e30f;
            }
        } else {
#pragma unroll
            for (int ni = 0; ni < 8; ni++)
#pragma unroll
                for (int e = 0; e < 4; e++) s[ni][e] *= scale;
        }

        float rmax0 = -1e30f, rmax1 = -1e30f;
#pragma unroll
        for (int ni = 0; ni < 8; ni++) {
            rmax0 = fmaxf(rmax0, fmaxf(s[ni][0], s[ni][1]));
            rmax1 = fmaxf(rmax1, fmaxf(s[ni][2], s[ni][3]));
        }
        rmax0 = fmaxf(rmax0, __shfl_xor_sync(0xffffffffu, rmax0, 1));
        rmax0 = fmaxf(rmax0, __shfl_xor_sync(0xffffffffu, rmax0, 2));
        rmax1 = fmaxf(rmax1, __shfl_xor_sync(0xffffffffu, rmax1, 1));
        rmax1 = fmaxf(rmax1, __shfl_xor_sync(0xffffffffu, rmax1, 2));

        const float mn0 = fmaxf(m0, rmax0);
        const float mn1 = fmaxf(m1, rmax1);
        const float corr0 = __expf(m0 - mn0);
        const float corr1 = __expf(m1 - mn1);

        float ps0 = 0.f, ps1 = 0.f;
#pragma unroll
        for (int ni = 0; ni < 8; ni++) {
            s[ni][0] = __expf(s[ni][0] - mn0);
            s[ni][1] = __expf(s[ni][1] - mn0);
            s[ni][2] = __expf(s[ni][2] - mn1);
            s[ni][3] = __expf(s[ni][3] - mn1);
            ps0 += s[ni][0] + s[ni][1];
            ps1 += s[ni][2] + s[ni][3];
        }
        ps0 += __shfl_xor_sync(0xffffffffu, ps0, 1);
        ps0 += __shfl_xor_sync(0xffffffffu, ps0, 2);
        ps1 += __shfl_xor_sync(0xffffffffu, ps1, 1);
        ps1 += __shfl_xor_sync(0xffffffffu, ps1, 2);

        l0 = l0 * corr0 + ps0;  m0 = mn0;
        l1 = l1 * corr1 + ps1;  m1 = mn1;

#pragma unroll
        for (int ni = 0; ni < 8; ni++) {
            o[ni][0] *= corr0; o[ni][1] *= corr0;
            o[ni][2] *= corr1; o[ni][3] *= corr1;
        }

        {
            float* p0 = &Ps[(w * 16 + gr) * AST + 2 * gc];
            float* p1 = p0 + 8 * AST;
#pragma unroll
            for (int ni = 0; ni < 8; ni++) {
                *(float2*)(p0 + ni * 8) =
                    make_float2(to_tf32(s[ni][0]), to_tf32(s[ni][1]));
                *(float2*)(p1 + ni * 8) =
                    make_float2(to_tf32(s[ni][2]), to_tf32(s[ni][3]));
            }
        }
        __syncwarp();

#pragma unroll
        for (int ks = 0; ks < 8; ks++) {
            const float* ap = &Ps[(w * 16 + gr) * AST + ks * 8 + gc];
            float af[4];
            af[0] = ap[0];
            af[1] = ap[8 * AST];
            af[2] = ap[4];
            af[3] = ap[8 * AST + 4];
            const float* v0 = &Vs[(ks * 8 + gc) * AST + gr];
            const float* v1 = &Vs[(ks * 8 + gc + 4) * AST + gr];
            float bf[8][2];
#pragma unroll
            for (int ni = 0; ni < 8; ni++) {
                bf[ni][0] = v0[ni * 8];
                bf[ni][1] = v1[ni * 8];
            }
#pragma unroll
            for (int ni = 0; ni < 8; ni++)
                mma_tf32(o[ni], af, bf[ni]);
        }
    }

    const float inv0 = 1.f / l0;
    const float inv1 = 1.f / l1;
    const int p0 = ((gc & 1) << 2) | (gc >> 1);
#pragma unroll
    for (int ni = 0; ni < 8; ni++) {
        const int c = ni * 8;
        float* r0 = (float*)(O + base + (size_t)qg0 * HD_ + c);
        float* r1 = (float*)(O + base + (size_t)qg1 * HD_ + c);
        r0[p0]     = to_tf32(o[ni][0] * inv0);
        r0[p0 + 2] = to_tf32(o[ni][1] * inv0);
        r1[p0]     = to_tf32(o[ni][2] * inv1);
        r1[p0 + 2] = to_tf32(o[ni][3] * inv1);
    }
}

// ===========================================================================
// Host side
// ===========================================================================
extern "C" void kernel_launch(void* const* d_in, const int* in_sizes, int n_in,
                              void* d_out, int out_size)
{
    const float* residual = (const float*)d_in[0];
    const float* Wq = (const float*)d_in[1];
    const float* Wk = (const float*)d_in[2];
    const float* Wv = (const float*)d_in[3];
    const float* Wo = (const float*)d_in[4];
    float* out = (float*)d_out;

    float *q, *k, *v, *attn, *rr, *wq, *wk, *wv, *woT;
    cudaGetSymbolAddress((void**)&q,    g_q);
    cudaGetSymbolAddress((void**)&k,    g_k);
    cudaGetSymbolAddress((void**)&v,    g_v);
    cudaGetSymbolAddress((void**)&attn, g_attn);
    cudaGetSymbolAddress((void**)&rr,   g_rr);
    cudaGetSymbolAddress((void**)&wq,   g_wq);
    cudaGetSymbolAddress((void**)&wk,   g_wk);
    cudaGetSymbolAddress((void**)&wv,   g_wv);
    cudaGetSymbolAddress((void**)&woT,  g_woT);

    cudaFuncSetAttribute(attn_mma,
                         cudaFuncAttributeMaxDynamicSharedMemorySize,
                         ATTN_SMEM_BYTES);

    // Round + permute GEMM operands
    round_perm_k<<<QKV_ELEMS / 8 / 256, 256>>>(residual, rr, QKV_ELEMS / 8);
    round_perm_w3<<<dim3(D_ * D_ / 8 / 256, 1, 3), 256>>>(Wq, Wk, Wv,
                                                          wq, wk, wv,
                                                          D_ * D_ / 8);
    transpose_round_perm<<<dim3(32, 32), dim3(32, 8)>>>(Wo, woT);

    // Fused QKV projections (tf32-rounded outputs), 512-thread CTAs
    dim3 gqkv(D_ / 128, M_ / 128, 3);
    gemm_mma_qkv<<<gqkv, 512>>>(rr, wq, wk, wv, q, k, v, M_, D_, D_);

    // Causal flash attention (LPT order)
    dim3 gattn(S_ / 128, B_ * H_);
    attn_mma<<<gattn, 256, ATTN_SMEM_BYTES>>>(q, k, v, attn);

    // Output projection, 512-thread CTAs
    dim3 gg(D_ / 128, M_ / 128);
    gemm_mma_nt<<<gg, 512>>>(attn, woT, out, M_, D_, D_);
}

// round 11
// speedup vs baseline: 1.1137x; 1.1044x over previous
#include <cuda_runtime.h>
#include <cuda_bf16.h>
#include <cstdint>

// Problem: B=2, S=2048, D=1024, H=16, Dh=64, fp32.
//
// k-permutation (within each 8-col group of a contraction dim):
// input col i stored at pos(i) = i<4 ? 2i : 2(i-4)+1. Applied to BOTH
// operands -> dot invariant. mma frag cols {gc, gc+4} become one LDS.64.
// Used for: GEMM K-dims, q/k dh-dim (S-phase), P kv-dim (PV-phase),
// attn-out he-dim (out-proj A operand).

#define B_   2
#define S_   2048
#define D_   1024
#define H_   16
#define DH_  64
#define HD_  (H_ * DH_)          // 1024
#define M_   (B_ * S_)           // 4096

#define QKV_ELEMS (B_ * S_ * HD_)

__device__ float g_q[QKV_ELEMS];      // rounded + dh-permuted
__device__ float g_k[QKV_ELEMS];      // rounded + dh-permuted
__device__ float g_v[QKV_ELEMS];      // rounded (plain)
__device__ float g_attn[QKV_ELEMS];   // rounded + he-permuted
__device__ float g_rr[QKV_ELEMS];     // rounded + k-permuted residual
__device__ float g_wq[D_ * D_];
__device__ float g_wk[D_ * D_];
__device__ float g_wv[D_ * D_];
__device__ float g_woT[D_ * D_];      // rounded + k-permuted Wo^T

__device__ __forceinline__ float to_tf32(float x) {
    uint32_t r;
    asm("cvt.rna.tf32.f32 %0, %1;" : "=r"(r) : "f"(x));
    return __uint_as_float(r);
}

// mma.sync m16n8k8 tf32 (fragment mapping validated R4-R10):
// A: a0=A[gr][gc] a1=A[gr+8][gc] a2=A[gr][gc+4] a3=A[gr+8][gc+4]
// B: b0=B[n=gr][k=gc] b1=B[n=gr][k=gc+4]
// C: c0=C[gr][2gc] c1=C[gr][2gc+1] c2=C[gr+8][2gc] c3=C[gr+8][2gc+1]
__device__ __forceinline__ void mma_tf32(float* d, const float* a, const float* b) {
    asm volatile(
        "mma.sync.aligned.m16n8k8.row.col.f32.tf32.tf32.f32 "
        "{%0,%1,%2,%3}, {%4,%5,%6,%7}, {%8,%9}, {%0,%1,%2,%3};"
        : "+f"(d[0]), "+f"(d[1]), "+f"(d[2]), "+f"(d[3])
        : "r"(__float_as_uint(a[0])), "r"(__float_as_uint(a[1])),
          "r"(__float_as_uint(a[2])), "r"(__float_as_uint(a[3])),
          "r"(__float_as_uint(b[0])), "r"(__float_as_uint(b[1])));
}

// ===========================================================================
// tf32 mma GEMM: C[M,N] = A[M,K] . B[N,K]^T  — R8 body (best measured).
// 128x128 tile, BK=32, 256 threads, 8 warps @ 64x32, GST=40.
// OUT_MODE: 0 = plain fp32 store, 1 = tf32-rounded, 2 = rounded + N-permuted.
// ===========================================================================
#define GST 40

template <int OUT_MODE>
__device__ __forceinline__ void gemm_body(
    const float* __restrict__ A, const float* __restrict__ B,
    float* __restrict__ C, int M, int N, int K)
{
    __shared__ float As[128 * GST];
    __shared__ float Bs[128 * GST];

    const int tid = threadIdx.x;
    const int lane = tid & 31;
    const int w = tid >> 5;
    const int wm = (w & 1) * 64;
    const int wn = (w >> 1) * 32;
    const int row0 = blockIdx.y * 128;
    const int col0 = blockIdx.x * 128;

    const int ar = tid >> 3;
    const int ac = (tid & 7) * 4;

    const float* Ap = A + (size_t)(row0 + ar) * K + ac;
    const float* Bp = B + (size_t)(col0 + ar) * K + ac;

    float4 pa[4], pb[4];
#pragma unroll
    for (int p = 0; p < 4; p++) {
        pa[p] = *(const float4*)(Ap + (size_t)p * 32 * K);
        pb[p] = *(const float4*)(Bp + (size_t)p * 32 * K);
    }

    float acc[4][4][4];
#pragma unroll
    for (int mi = 0; mi < 4; mi++)
#pragma unroll
        for (int ni = 0; ni < 4; ni++)
#pragma unroll
            for (int e = 0; e < 4; e++) acc[mi][ni][e] = 0.f;

    const int gr = lane >> 2;
    const int gc = lane & 3;
    const int iters = K / 32;

    for (int kt = 0;;) {
#pragma unroll
        for (int p = 0; p < 4; p++) {
            const int r = ar + p * 32;
            *(float4*)&As[r * GST + ac] = pa[p];
            *(float4*)&Bs[r * GST + ac] = pb[p];
        }
        __syncthreads();

        kt++;
        if (kt < iters) {
#pragma unroll
            for (int p = 0; p < 4; p++) {
                pa[p] = *(const float4*)(Ap + kt * 32 + (size_t)p * 32 * K);
                pb[p] = *(const float4*)(Bp + kt * 32 + (size_t)p * 32 * K);
            }
        }

#pragma unroll
        for (int ks = 0; ks < 4; ks++) {
            const int k0 = ks * 8 + 2 * gc;
            float af[4][4];
#pragma unroll
            for (int mi = 0; mi < 4; mi++) {
                const float2 alo = *(const float2*)&As[(wm + mi * 16 + gr) * GST + k0];
                const float2 ahi = *(const float2*)&As[(wm + mi * 16 + gr + 8) * GST + k0];
                af[mi][0] = alo.x; af[mi][1] = ahi.x;
                af[mi][2] = alo.y; af[mi][3] = ahi.y;
            }
            float bf[4][2];
#pragma unroll
            for (int ni = 0; ni < 4; ni++) {
                const float2 b2 = *(const float2*)&Bs[(wn + ni * 8 + gr) * GST + k0];
                bf[ni][0] = b2.x; bf[ni][1] = b2.y;
            }
#pragma unroll
            for (int mi = 0; mi < 4; mi++)
#pragma unroll
                for (int ni = 0; ni < 4; ni++)
                    mma_tf32(acc[mi][ni], af[mi], bf[ni]);
        }

        if (kt >= iters) break;
        __syncthreads();
    }

    const int p0 = ((gc & 1) << 2) | (gc >> 1);   // pos(2gc); pos(2gc+1)=p0+2
#pragma unroll
    for (int mi = 0; mi < 4; mi++) {
        const int r = row0 + wm + mi * 16 + gr;
#pragma unroll
        for (int ni = 0; ni < 4; ni++) {
            if (OUT_MODE == 2) {
                const int cb = col0 + wn + ni * 8;
                float* r0 = C + (size_t)r * N + cb;
                float* r1 = C + (size_t)(r + 8) * N + cb;
                r0[p0]     = to_tf32(acc[mi][ni][0]);
                r0[p0 + 2] = to_tf32(acc[mi][ni][1]);
                r1[p0]     = to_tf32(acc[mi][ni][2]);
                r1[p0 + 2] = to_tf32(acc[mi][ni][3]);
            } else {
                const int c = col0 + wn + ni * 8 + 2 * gc;
                if (OUT_MODE == 1) {
#pragma unroll
                    for (int e = 0; e < 4; e++)
                        acc[mi][ni][e] = to_tf32(acc[mi][ni][e]);
                }
                *(float2*)(C + (size_t)r * N + c) =
                    make_float2(acc[mi][ni][0], acc[mi][ni][1]);
                *(float2*)(C + (size_t)(r + 8) * N + c) =
                    make_float2(acc[mi][ni][2], acc[mi][ni][3]);
            }
        }
    }
}

__global__ void __launch_bounds__(256) gemm_mma_nt(
    const float* __restrict__ A, const float* __restrict__ B,
    float* __restrict__ C, int M, int N, int K)
{
    gemm_body<0>(A, B, C, M, N, K);
}

__global__ void __launch_bounds__(256) gemm_mma_qkv(
    const float* __restrict__ A,
    const float* __restrict__ Wq, const float* __restrict__ Wk,
    const float* __restrict__ Wv,
    float* __restrict__ q, float* __restrict__ k, float* __restrict__ v,
    int M, int N, int K)
{
    const int z = blockIdx.z;
    const float* Bp = (z == 0) ? Wq : (z == 1) ? Wk : Wv;
    float* Cp = (z == 0) ? q : (z == 1) ? k : v;
    if (z < 2)
        gemm_body<2>(A, Bp, Cp, M, N, K);   // q,k: rounded + dh-permuted
    else
        gemm_body<1>(A, Bp, Cp, M, N, K);   // v: rounded, plain
}

// ===========================================================================
// Pre-rounding + k-permutation kernels
// ===========================================================================
__global__ void round_perm_k(const float* __restrict__ in,
                             float* __restrict__ out, int n8)
{
    int i = blockIdx.x * blockDim.x + threadIdx.x;
    if (i < n8) {
        const float4 lo = *(const float4*)(in + (size_t)i * 8);
        const float4 hi = *(const float4*)(in + (size_t)i * 8 + 4);
        *(float4*)(out + (size_t)i * 8) =
            make_float4(to_tf32(lo.x), to_tf32(hi.x), to_tf32(lo.y), to_tf32(hi.y));
        *(float4*)(out + (size_t)i * 8 + 4) =
            make_float4(to_tf32(lo.z), to_tf32(hi.z), to_tf32(lo.w), to_tf32(hi.w));
    }
}

__global__ void round_perm_w3(const float* __restrict__ Wq,
                              const float* __restrict__ Wk,
                              const float* __restrict__ Wv,
                              float* __restrict__ oq, float* __restrict__ ok,
                              float* __restrict__ ov, int n8)
{
    const int z = blockIdx.z;
    const float* in = (z == 0) ? Wq : (z == 1) ? Wk : Wv;
    float* out = (z == 0) ? oq : (z == 1) ? ok : ov;
    int i = blockIdx.x * blockDim.x + threadIdx.x;
    if (i < n8) {
        const float4 lo = *(const float4*)(in + (size_t)i * 8);
        const float4 hi = *(const float4*)(in + (size_t)i * 8 + 4);
        *(float4*)(out + (size_t)i * 8) =
            make_float4(to_tf32(lo.x), to_tf32(hi.x), to_tf32(lo.y), to_tf32(hi.y));
        *(float4*)(out + (size_t)i * 8 + 4) =
            make_float4(to_tf32(lo.z), to_tf32(hi.z), to_tf32(lo.w), to_tf32(hi.w));
    }
}

__global__ void transpose_round_perm(const float* __restrict__ in,
                                     float* __restrict__ out)
{
    __shared__ float t[32][33];
    const int bx = blockIdx.x * 32, by = blockIdx.y * 32;
    const int x = threadIdx.x, y = threadIdx.y;
#pragma unroll
    for (int j = 0; j < 32; j += 8)
        t[y + j][x] = in[(size_t)(by + y + j) * D_ + bx + x];
    __syncthreads();
    const int xi = x & 7;
    const int px = (x & 24) | (xi < 4 ? 2 * xi : 2 * (xi - 4) + 1);
#pragma unroll
    for (int j = 0; j < 32; j += 8)
        out[(size_t)(bx + y + j) * D_ + by + px] = to_tf32(t[x][y + j]);
}

// ===========================================================================
// Flash attention (causal) tf32 mma.
// R11: q/k arrive dh-PERMUTED (S-phase frags = LDS.64); P stored permuted
// (PV A-frags = LDS.64); AST=72 for conflict-free LDS.64 (banks 8gr+2gc).
// V plain. LPT block order. Inputs pre-rounded.
// ===========================================================================
#define AST 72
#define ATTN_SMEM_FLOATS (64 * AST + 64 * AST + 128 * AST)
#define ATTN_SMEM_BYTES  (ATTN_SMEM_FLOATS * 4)   // 73728

__global__ void __launch_bounds__(256) attn_mma(
    const float* __restrict__ Q, const float* __restrict__ K,
    const float* __restrict__ V, float* __restrict__ O)
{
    extern __shared__ float sma[];
    float* Ks = sma;                 // [64][AST]  (dh-permuted rows)
    float* Vs = sma + 64 * AST;      // [64][AST]  (plain)
    float* Ps = sma + 128 * AST;     // [128][AST] (Q staging / permuted P)

    const int tid = threadIdx.x;
    const int lane = tid & 31;
    const int w = tid >> 5;
    const int gr = lane >> 2;
    const int gc = lane & 3;

    const int qt = (gridDim.x - 1) - blockIdx.x;   // LPT: heavy blocks first
    const int bh = blockIdx.y;
    const int b = bh >> 4, h = bh & 15;
    const int q0 = qt * 128;
    const size_t base = (size_t)b * S_ * HD_ + (size_t)h * DH_;

    // Stage Q (rounded + dh-permuted) into Ps
    {
        const int r = tid >> 4;
        const int c = (tid & 15) << 2;
#pragma unroll
        for (int rr = 0; rr < 128; rr += 16) {
            *(float4*)&Ps[(rr + r) * AST + c] =
                *(const float4*)(Q + base + (size_t)(q0 + rr + r) * HD_ + c);
        }
    }
    __syncthreads();

    // Q A-frags via LDS.64 (permuted layout: cols {gc, gc+4} adjacent)
    float qf[8][4];
#pragma unroll
    for (int ks = 0; ks < 8; ks++) {
        const int k0 = ks * 8 + 2 * gc;
        const float2 qlo = *(const float2*)&Ps[(w * 16 + gr) * AST + k0];
        const float2 qhi = *(const float2*)&Ps[(w * 16 + gr + 8) * AST + k0];
        qf[ks][0] = qlo.x; qf[ks][1] = qhi.x;
        qf[ks][2] = qlo.y; qf[ks][3] = qhi.y;
    }
    __syncthreads();   // qf read before Ps is overwritten with P

    float o[8][4];
#pragma unroll
    for (int ni = 0; ni < 8; ni++)
#pragma unroll
        for (int e = 0; e < 4; e++) o[ni][e] = 0.f;
    float m0 = -1e30f, m1 = -1e30f, l0 = 0.f, l1 = 0.f;

    const int qg0 = q0 + w * 16 + gr;
    const int qg1 = qg0 + 8;
    const int ktiles = 2 * qt + 2;
    const int p0 = ((gc & 1) << 2) | (gc >> 1);    // pos(2gc)

    for (int kt = 0; kt < ktiles; kt++) {
        const int kv0 = kt * 64;
        __syncthreads();
        {
            const int r = tid >> 4;
            const int c = (tid & 15) << 2;
#pragma unroll
            for (int rr = 0; rr < 64; rr += 16) {
                const int row = rr + r;
                *(float4*)&Ks[row * AST + c] =
                    *(const float4*)(K + base + (size_t)(kv0 + row) * HD_ + c);
                *(float4*)&Vs[row * AST + c] =
                    *(const float4*)(V + base + (size_t)(kv0 + row) * HD_ + c);
            }
        }
        __syncthreads();

        if (kv0 > q0 + w * 16 + 15) continue;

        // S = Q . K^T  (both dh-permuted -> B-frags are LDS.64)
        float s[8][4];
#pragma unroll
        for (int ni = 0; ni < 8; ni++)
#pragma unroll
            for (int e = 0; e < 4; e++) s[ni][e] = 0.f;

#pragma unroll
        for (int ks = 0; ks < 8; ks++) {
            const int k0 = ks * 8 + 2 * gc;
            float bf[8][2];
#pragma unroll
            for (int ni = 0; ni < 8; ni++) {
                const float2 b2 = *(const float2*)&Ks[(ni * 8 + gr) * AST + k0];
                bf[ni][0] = b2.x;
                bf[ni][1] = b2.y;
            }
#pragma unroll
            for (int ni = 0; ni < 8; ni++)
                mma_tf32(s[ni], qf[ks], bf[ni]);
        }

        const float scale = 0.125f;
        if (kv0 + 63 > q0 + w * 16) {
#pragma unroll
            for (int ni = 0; ni < 8; ni++) {
                const int c0 = kv0 + ni * 8 + 2 * gc;
                s[ni][0] = (c0     <= qg0) ? s[ni][0] * scale : -1e30f;
                s[ni][1] = (c0 + 1 <= qg0) ? s[ni][1] * scale : -1e30f;
                s[ni][2] = (c0     <= qg1) ? s[ni][2] * scale : -1e30f;
                s[ni][3] = (c0 + 1 <= qg1) ? s[ni][3] * scale : -1e30f;
            }
        } else {
#pragma unroll
            for (int ni = 0; ni < 8; ni++)
#pragma unroll
                for (int e = 0; e < 4; e++) s[ni][e] *= scale;
        }

        float rmax0 = -1e30f, rmax1 = -1e30f;
#pragma unroll
        for (int ni = 0; ni < 8; ni++) {
            rmax0 = fmaxf(rmax0, fmaxf(s[ni][0], s[ni][1]));
            rmax1 = fmaxf(rmax1, fmaxf(s[ni][2], s[ni][3]));
        }
        rmax0 = fmaxf(rmax0, __shfl_xor_sync(0xffffffffu, rmax0, 1));
        rmax0 = fmaxf(rmax0, __shfl_xor_sync(0xffffffffu, rmax0, 2));
        rmax1 = fmaxf(rmax1, __shfl_xor_sync(0xffffffffu, rmax1, 1));
        rmax1 = fmaxf(rmax1, __shfl_xor_sync(0xffffffffu, rmax1, 2));

        const float mn0 = fmaxf(m0, rmax0);
        const float mn1 = fmaxf(m1, rmax1);
        const float corr0 = __expf(m0 - mn0);
        const float corr1 = __expf(m1 - mn1);

        float ps0 = 0.f, ps1 = 0.f;
#pragma unroll
        for (int ni = 0; ni < 8; ni++) {
            s[ni][0] = __expf(s[ni][0] - mn0);
            s[ni][1] = __expf(s[ni][1] - mn0);
            s[ni][2] = __expf(s[ni][2] - mn1);
            s[ni][3] = __expf(s[ni][3] - mn1);
            ps0 += s[ni][0] + s[ni][1];
            ps1 += s[ni][2] + s[ni][3];
        }
        ps0 += __shfl_xor_sync(0xffffffffu, ps0, 1);
        ps0 += __shfl_xor_sync(0xffffffffu, ps0, 2);
        ps1 += __shfl_xor_sync(0xffffffffu, ps1, 1);
        ps1 += __shfl_xor_sync(0xffffffffu, ps1, 2);

        l0 = l0 * corr0 + ps0;  m0 = mn0;
        l1 = l1 * corr1 + ps1;  m1 = mn1;

#pragma unroll
        for (int ni = 0; ni < 8; ni++) {
            o[ni][0] *= corr0; o[ni][1] *= corr0;
            o[ni][2] *= corr1; o[ni][3] *= corr1;
        }

        // P -> Ps at PERMUTED positions (col 2gc -> p0, col 2gc+1 -> p0+2)
        {
            float* pr0 = &Ps[(w * 16 + gr) * AST];
            float* pr1 = pr0 + 8 * AST;
#pragma unroll
            for (int ni = 0; ni < 8; ni++) {
                pr0[ni * 8 + p0]     = to_tf32(s[ni][0]);
                pr0[ni * 8 + p0 + 2] = to_tf32(s[ni][1]);
                pr1[ni * 8 + p0]     = to_tf32(s[ni][2]);
                pr1[ni * 8 + p0 + 2] = to_tf32(s[ni][3]);
            }
        }
        __syncwarp();

        // O += P . V  (P permuted -> A-frags are LDS.64; V frags LDS.32)
#pragma unroll
        for (int ks = 0; ks < 8; ks++) {
            const int k0 = ks * 8 + 2 * gc;
            const float2 plo = *(const float2*)&Ps[(w * 16 + gr) * AST + k0];
            const float2 phi = *(const float2*)&Ps[(w * 16 + gr + 8) * AST + k0];
            float af[4];
            af[0] = plo.x; af[1] = phi.x;
            af[2] = plo.y; af[3] = phi.y;
            const float* v0 = &Vs[(ks * 8 + gc) * AST + gr];
            const float* v1 = &Vs[(ks * 8 + gc + 4) * AST + gr];
            float bf[8][2];
#pragma unroll
            for (int ni = 0; ni < 8; ni++) {
                bf[ni][0] = v0[ni * 8];
                bf[ni][1] = v1[ni * 8];
            }
#pragma unroll
            for (int ni = 0; ni < 8; ni++)
                mma_tf32(o[ni], af, bf[ni]);
        }
    }

    // Epilogue: rounded + he-permuted stores (out-proj consumes as A).
    const float inv0 = 1.f / l0;
    const float inv1 = 1.f / l1;
#pragma unroll
    for (int ni = 0; ni < 8; ni++) {
        const int c = ni * 8;
        float* r0 = (float*)(O + base + (size_t)qg0 * HD_ + c);
        float* r1 = (float*)(O + base + (size_t)qg1 * HD_ + c);
        r0[p0]     = to_tf32(o[ni][0] * inv0);
        r0[p0 + 2] = to_tf32(o[ni][1] * inv0);
        r1[p0]     = to_tf32(o[ni][2] * inv1);
        r1[p0 + 2] = to_tf32(o[ni][3] * inv1);
    }
}

// ===========================================================================
// Host side
// ===========================================================================
extern "C" void kernel_launch(void* const* d_in, const int* in_sizes, int n_in,
                              void* d_out, int out_size)
{
    const float* residual = (const float*)d_in[0];
    const float* Wq = (const float*)d_in[1];
    const float* Wk = (const float*)d_in[2];
    const float* Wv = (const float*)d_in[3];
    const float* Wo = (const float*)d_in[4];
    float* out = (float*)d_out;

    float *q, *k, *v, *attn, *rr, *wq, *wk, *wv, *woT;
    cudaGetSymbolAddress((void**)&q,    g_q);
    cudaGetSymbolAddress((void**)&k,    g_k);
    cudaGetSymbolAddress((void**)&v,    g_v);
    cudaGetSymbolAddress((void**)&attn, g_attn);
    cudaGetSymbolAddress((void**)&rr,   g_rr);
    cudaGetSymbolAddress((void**)&wq,   g_wq);
    cudaGetSymbolAddress((void**)&wk,   g_wk);
    cudaGetSymbolAddress((void**)&wv,   g_wv);
    cudaGetSymbolAddress((void**)&woT,  g_woT);

    cudaFuncSetAttribute(attn_mma,
                         cudaFuncAttributeMaxDynamicSharedMemorySize,
                         ATTN_SMEM_BYTES);

    // Round + permute GEMM operands
    round_perm_k<<<QKV_ELEMS / 8 / 256, 256>>>(residual, rr, QKV_ELEMS / 8);
    round_perm_w3<<<dim3(D_ * D_ / 8 / 256, 1, 3), 256>>>(Wq, Wk, Wv,
                                                          wq, wk, wv,
                                                          D_ * D_ / 8);
    transpose_round_perm<<<dim3(32, 32), dim3(32, 8)>>>(Wo, woT);

    // Fused QKV projections (q/k dh-permuted, v plain; all rounded)
    dim3 gqkv(D_ / 128, M_ / 128, 3);
    gemm_mma_qkv<<<gqkv, 256>>>(rr, wq, wk, wv, q, k, v, M_, D_, D_);

    // Causal flash attention (LPT order, LDS.64 fragments)
    dim3 gattn(S_ / 128, B_ * H_);
    attn_mma<<<gattn, 256, ATTN_SMEM_BYTES>>>(q, k, v, attn);

    // Output projection
    dim3 gg(D_ / 128, M_ / 128);
    gemm_mma_nt<<<gg, 256>>>(attn, woT, out, M_, D_, D_);
}